// round 1
// baseline (speedup 1.0000x reference)
#include <cuda_runtime.h>
#include <math.h>

#define BSZ   2048
#define DETER 8192
#define STOCH 1024
#define ACTD  32
#define HID   1024
#define GRP   8
#define DPG   1024
#define EPSV  1e-6f

// ---------------- scratch (static device arrays; no allocations) -------------
__device__ float g_xc[BSZ * 3 * HID];          // concat(x1,x2,x3)  (also holds pre-norm GEMM outputs)
__device__ float g_H [BSZ * DETER];            // dyn block-matmul output (pre-norm)
__device__ float g_hn[BSZ * DETER];            // rmsnorm(H)
__device__ float g_X [BSZ * GRP * 3 * DPG];    // out block-matmul output (B x 24576)

// ---------------- block reduction --------------------------------------------
__device__ __forceinline__ float block_sum(float v) {
    __shared__ float red[32];
    int lane = threadIdx.x & 31, w = threadIdx.x >> 5;
    #pragma unroll
    for (int o = 16; o; o >>= 1) v += __shfl_xor_sync(0xffffffffu, v, o);
    if (lane == 0) red[w] = v;
    __syncthreads();
    int nw = blockDim.x >> 5;
    float s = (threadIdx.x < (unsigned)nw) ? red[threadIdx.x] : 0.f;
    if (w == 0) {
        #pragma unroll
        for (int o = 16; o; o >>= 1) s += __shfl_xor_sync(0xffffffffu, s, o);
        if (lane == 0) red[0] = s;
    }
    __syncthreads();
    return red[0];
}

// ---------------- generic fp32 tiled GEMM ------------------------------------
// C[z] (M x N) = A_cat[z] (M x K) * Bw[z] (K x N) + bias
// A columns [0, ksplit) come from A (stride lda), columns [ksplit, K) from A2
// (stride lda2). All of M, N divisible by 128; K, ksplit divisible by 8.
#define BM 128
#define BN 128
#define BK 8
#define TM 8
#define TN 8

__global__ __launch_bounds__(256)
void sgemm(int K, int ksplit,
           const float* __restrict__ A,  int lda,  long long sAz,
           const float* __restrict__ A2, int lda2, long long sA2z,
           const float* __restrict__ Bw, int ldb,  long long sBz,
           const float* __restrict__ bias,
           float* __restrict__ C, int ldc, long long sCz)
{
    int z = blockIdx.z;
    A  += (size_t)z * sAz;
    A2 += (size_t)z * sA2z;
    Bw += (size_t)z * sBz;
    C  += (size_t)z * sCz;

    const int row0 = blockIdx.y * BM;
    const int col0 = blockIdx.x * BN;
    const int tid  = threadIdx.x;

    __shared__ float As[BK][BM];
    __shared__ float Bs[BK][BN];

    // A tile load: 128 rows x 8 cols -> thread loads one float4
    const int aRow = tid >> 1;          // 0..127
    const int aCol = (tid & 1) * 4;     // 0 or 4
    // B tile load: 8 rows x 128 cols -> thread loads one float4
    const int bRow = tid >> 5;          // 0..7
    const int bCol = (tid & 31) * 4;    // 0..124

    const int tm = (tid >> 4) * TM;     // 0..120
    const int tn = (tid & 15) * TN;     // 0..120

    float acc[TM][TN];
    #pragma unroll
    for (int i = 0; i < TM; i++)
        #pragma unroll
        for (int j = 0; j < TN; j++) acc[i][j] = 0.f;

    for (int k0 = 0; k0 < K; k0 += BK) {
        const float* Asrc; int kloc, ldA;
        if (k0 < ksplit) { Asrc = A;  kloc = k0;          ldA = lda;  }
        else             { Asrc = A2; kloc = k0 - ksplit; ldA = lda2; }

        float4 av = *(const float4*)(Asrc + (size_t)(row0 + aRow) * ldA + kloc + aCol);
        As[aCol + 0][aRow] = av.x;
        As[aCol + 1][aRow] = av.y;
        As[aCol + 2][aRow] = av.z;
        As[aCol + 3][aRow] = av.w;

        float4 bv = *(const float4*)(Bw + (size_t)(k0 + bRow) * ldb + col0 + bCol);
        *(float4*)&Bs[bRow][bCol] = bv;

        __syncthreads();

        #pragma unroll
        for (int kk = 0; kk < BK; kk++) {
            float ar[TM], br[TN];
            #pragma unroll
            for (int i = 0; i < TM; i++) ar[i] = As[kk][tm + i];
            #pragma unroll
            for (int j = 0; j < TN; j++) br[j] = Bs[kk][tn + j];
            #pragma unroll
            for (int i = 0; i < TM; i++)
                #pragma unroll
                for (int j = 0; j < TN; j++)
                    acc[i][j] = fmaf(ar[i], br[j], acc[i][j]);
        }
        __syncthreads();
    }

    float bb[TN];
    #pragma unroll
    for (int j = 0; j < TN; j++) bb[j] = bias ? bias[col0 + tn + j] : 0.f;

    #pragma unroll
    for (int i = 0; i < TM; i++) {
        float* Cp = C + (size_t)(row0 + tm + i) * ldc + col0 + tn;
        #pragma unroll
        for (int j = 0; j < TN; j += 4) {
            float4 v;
            v.x = acc[i][j + 0] + bb[j + 0];
            v.y = acc[i][j + 1] + bb[j + 1];
            v.z = acc[i][j + 2] + bb[j + 2];
            v.w = acc[i][j + 3] + bb[j + 3];
            *(float4*)(Cp + j) = v;
        }
    }
}

// ---------------- tiny action GEMM (K=32) into xc[:, 2048:3072] --------------
__global__ __launch_bounds__(256)
void act_gemm(const float* __restrict__ action, const float* __restrict__ W3,
              const float* __restrict__ b3, float* __restrict__ xc)
{
    int b = blockIdx.x;
    __shared__ float a_s[ACTD];
    int t = threadIdx.x;
    if (t < ACTD) {
        float v = action[(size_t)b * ACTD + t];
        float m = fabsf(v); m = m > 1.f ? m : 1.f;
        a_s[t] = v / m;
    }
    __syncthreads();
    for (int n = t; n < HID; n += 256) {
        float s = b3[n];
        #pragma unroll
        for (int k = 0; k < ACTD; k++) s = fmaf(a_s[k], W3[k * HID + n], s);
        xc[(size_t)b * (3 * HID) + 2 * HID + n] = s;
    }
}

// ---------------- rmsnorm + silu, in place on one 1024-wide segment of xc ----
__global__ __launch_bounds__(256)
void rms_silu(float* __restrict__ xc,
              const float* __restrict__ w1, const float* __restrict__ w2,
              const float* __restrict__ w3)
{
    int b = blockIdx.x, s = blockIdx.y;
    const float* w = (s == 0) ? w1 : (s == 1) ? w2 : w3;
    float* seg = xc + (size_t)b * (3 * HID) + (size_t)s * HID;
    int i0 = threadIdx.x * 4;
    float4 v = *(float4*)(seg + i0);
    float ss = v.x * v.x + v.y * v.y + v.z * v.z + v.w * v.w;
    float tot = block_sum(ss);
    float scale = rsqrtf(tot * (1.0f / HID) + EPSV);
    float4 g = *(const float4*)(w + i0);
    float4 o;
    float y;
    y = v.x * scale * g.x; o.x = y / (1.f + expf(-y));
    y = v.y * scale * g.y; o.y = y / (1.f + expf(-y));
    y = v.z * scale * g.z; o.z = y / (1.f + expf(-y));
    y = v.w * scale * g.w; o.w = y / (1.f + expf(-y));
    *(float4*)(seg + i0) = o;
}

// ---------------- rmsnorm over 8192 (H -> hn) --------------------------------
__global__ __launch_bounds__(256)
void rms_deter(const float* __restrict__ H, const float* __restrict__ gdyn,
               float* __restrict__ hn)
{
    int b = blockIdx.x;
    const float* row = H + (size_t)b * DETER;
    float4 v[8];
    float ss = 0.f;
    #pragma unroll
    for (int c = 0; c < 8; c++) {
        int d = threadIdx.x * 4 + c * 1024;
        v[c] = *(const float4*)(row + d);
        ss += v[c].x * v[c].x + v[c].y * v[c].y + v[c].z * v[c].z + v[c].w * v[c].w;
    }
    float tot = block_sum(ss);
    float scale = rsqrtf(tot * (1.0f / DETER) + EPSV);
    float* out = hn + (size_t)b * DETER;
    #pragma unroll
    for (int c = 0; c < 8; c++) {
        int d = threadIdx.x * 4 + c * 1024;
        float4 g = *(const float4*)(gdyn + d);
        float4 o;
        o.x = v[c].x * scale * g.x;
        o.y = v[c].y * scale * g.y;
        o.z = v[c].z * scale * g.z;
        o.w = v[c].w * scale * g.w;
        *(float4*)(out + d) = o;
    }
}

// ---------------- gates ------------------------------------------------------
__device__ __forceinline__ float sigf(float x) { return 1.f / (1.f + expf(-x)); }

__global__ __launch_bounds__(256)
void gates(const float* __restrict__ X, const float* __restrict__ deter,
           float* __restrict__ out)
{
    size_t t = (size_t)blockIdx.x * blockDim.x + threadIdx.x;   // float4 index
    size_t e = t * 4;                                           // element index
    int b = (int)(e / DETER);
    int d = (int)(e % DETER);
    int g = d >> 10, o = d & 1023;
    size_t xb = (size_t)b * (GRP * 3 * DPG) + (size_t)g * (3 * DPG) + o;
    float4 R = *(const float4*)(X + xb);
    float4 Cc = *(const float4*)(X + xb + DPG);
    float4 U = *(const float4*)(X + xb + 2 * DPG);
    float4 D = *(const float4*)(deter + (size_t)b * DETER + d);
    float4 r;
    float rs, cd, up;
    rs = sigf(R.x); cd = tanhf(rs * Cc.x); up = sigf(U.x - 1.f); r.x = up * cd + (1.f - up) * D.x;
    rs = sigf(R.y); cd = tanhf(rs * Cc.y); up = sigf(U.y - 1.f); r.y = up * cd + (1.f - up) * D.y;
    rs = sigf(R.z); cd = tanhf(rs * Cc.z); up = sigf(U.z - 1.f); r.z = up * cd + (1.f - up) * D.z;
    rs = sigf(R.w); cd = tanhf(rs * Cc.w); up = sigf(U.w - 1.f); r.w = up * cd + (1.f - up) * D.w;
    *(float4*)(out + e) = r;
}

// ---------------- launch -----------------------------------------------------
extern "C" void kernel_launch(void* const* d_in, const int* in_sizes, int n_in,
                              void* d_out, int out_size)
{
    const float* deter  = (const float*)d_in[0];
    const float* stoch  = (const float*)d_in[1];
    const float* action = (const float*)d_in[2];
    const float* W1     = (const float*)d_in[3];
    const float* b1     = (const float*)d_in[4];
    const float* W2     = (const float*)d_in[5];
    const float* b2     = (const float*)d_in[6];
    const float* W3     = (const float*)d_in[7];
    const float* b3     = (const float*)d_in[8];
    const float* g1     = (const float*)d_in[9];
    const float* g2     = (const float*)d_in[10];
    const float* g3     = (const float*)d_in[11];
    const float* Wdyn   = (const float*)d_in[12];
    const float* gdyn   = (const float*)d_in[13];
    const float* Wout   = (const float*)d_in[14];
    float* out          = (float*)d_out;

    float *xc, *H, *hn, *X;
    cudaGetSymbolAddress((void**)&xc, g_xc);
    cudaGetSymbolAddress((void**)&H,  g_H);
    cudaGetSymbolAddress((void**)&hn, g_hn);
    cudaGetSymbolAddress((void**)&X,  g_X);

    // GEMM1: x1pre = deter @ W1 + b1  -> xc[:, 0:1024]
    sgemm<<<dim3(HID / BN, BSZ / BM, 1), 256>>>(
        DETER, DETER, deter, DETER, 0, deter, DETER, 0,
        W1, HID, 0, b1, xc, 3 * HID, 0);

    // GEMM2: x2pre = stoch @ W2 + b2 -> xc[:, 1024:2048]
    sgemm<<<dim3(HID / BN, BSZ / BM, 1), 256>>>(
        STOCH, STOCH, stoch, STOCH, 0, stoch, STOCH, 0,
        W2, HID, 0, b2, xc + HID, 3 * HID, 0);

    // GEMM3: x3pre = norm(action) @ W3 + b3 -> xc[:, 2048:3072]
    act_gemm<<<BSZ, 256>>>(action, W3, b3, xc);

    // rmsnorm + silu on all three segments (in place)
    rms_silu<<<dim3(BSZ, 3), 256>>>(xc, g1, g2, g3);

    // GEMM4 (block-diagonal dyn): H[:, g*1024:(g+1)*1024] =
    //   [xc | deter_g] @ Wdyn[g]
    sgemm<<<dim3(DPG / BN, BSZ / BM, GRP), 256>>>(
        4096, 3 * HID,
        xc, 3 * HID, 0,
        deter, DETER, DPG,
        Wdyn, DPG, (long long)4096 * DPG,
        nullptr, H, DETER, DPG);

    // rmsnorm over 8192
    rms_deter<<<BSZ, 256>>>(H, gdyn, hn);

    // GEMM5 (block-diagonal out): X[:, g, :] = hn_g @ Wout[g]
    sgemm<<<dim3(3 * DPG / BN, BSZ / BM, GRP), 256>>>(
        DPG, DPG,
        hn, DETER, DPG,
        hn, DETER, DPG,
        Wout, 3 * DPG, (long long)DPG * 3 * DPG,
        nullptr, X, GRP * 3 * DPG, 3 * DPG);

    // gates
    size_t n4 = (size_t)BSZ * DETER / 4;
    gates<<<(unsigned)((n4 + 255) / 256), 256>>>(X, deter, out);
}

// round 3
// speedup vs baseline: 2.8829x; 2.8829x over previous
#include <cuda_runtime.h>
#include <math.h>
#include <stdint.h>

#define BSZ   2048
#define DETER 8192
#define STOCH 1024
#define ACTD  32
#define HID   1024
#define GRP   8
#define DPG   1024
#define EPSV  1e-6f

// ---------------- scratch (static device arrays; no allocations) -------------
__device__ float g_xc[BSZ * 3 * HID];
__device__ float g_H [BSZ * DETER];
__device__ float g_hn[BSZ * DETER];
__device__ float g_X [BSZ * GRP * 3 * DPG];

// ---------------- helpers ----------------------------------------------------
__device__ __forceinline__ uint32_t f2tf32(float f) {
    uint32_t r;
    asm("cvt.rna.tf32.f32 %0, %1;" : "=r"(r) : "f"(f));
    return r;
}

__device__ __forceinline__ void mma_tf32(float& c0, float& c1, float& c2, float& c3,
                                         uint32_t a0, uint32_t a1, uint32_t a2, uint32_t a3,
                                         uint32_t b0, uint32_t b1) {
    asm("mma.sync.aligned.m16n8k8.row.col.f32.tf32.tf32.f32 "
        "{%0,%1,%2,%3},{%4,%5,%6,%7},{%8,%9},{%0,%1,%2,%3};"
        : "+f"(c0), "+f"(c1), "+f"(c2), "+f"(c3)
        : "r"(a0), "r"(a1), "r"(a2), "r"(a3), "r"(b0), "r"(b1));
}

__device__ __forceinline__ float block_sum(float v) {
    __shared__ float red[32];
    int lane = threadIdx.x & 31, w = threadIdx.x >> 5;
    #pragma unroll
    for (int o = 16; o; o >>= 1) v += __shfl_xor_sync(0xffffffffu, v, o);
    if (lane == 0) red[w] = v;
    __syncthreads();
    int nw = blockDim.x >> 5;
    float s = (threadIdx.x < (unsigned)nw) ? red[threadIdx.x] : 0.f;
    if (w == 0) {
        #pragma unroll
        for (int o = 16; o; o >>= 1) s += __shfl_xor_sync(0xffffffffu, s, o);
        if (lane == 0) red[0] = s;
    }
    __syncthreads();
    return red[0];
}

// ---------------- TF32 tensor-core GEMM --------------------------------------
// C[z] (M x N) = A_cat[z] (M x K) * Bw[z] (K x N) + bias
// A columns [0, ksplit) from A (stride lda), [ksplit, K) from A2 (stride lda2).
// M, N divisible by 128; K, ksplit divisible by 32.
#define BM 128
#define BN 128
#define BK 32

// XOR swizzle: phys index into a [BK][128] float tile
#define SWZ(k, x) (((k) << 7) + ((x) ^ (((k) & 3) << 3)))

__global__ __launch_bounds__(256)
void tgemm(int K, int ksplit,
           const float* __restrict__ A,  int lda,  long long sAz,
           const float* __restrict__ A2, int lda2, long long sA2z,
           const float* __restrict__ Bw, int ldb,  long long sBz,
           const float* __restrict__ bias,
           float* __restrict__ C, int ldc, long long sCz)
{
    const int z = blockIdx.z;
    A  += (size_t)z * sAz;
    A2 += (size_t)z * sA2z;
    Bw += (size_t)z * sBz;
    C  += (size_t)z * sCz;

    const int row0 = blockIdx.y * BM;
    const int col0 = blockIdx.x * BN;
    const int tid  = threadIdx.x;
    const int lane = tid & 31;
    const int warp = tid >> 5;
    const int wm   = (warp >> 2) * 64;   // warp row origin (0 or 64)
    const int wn   = (warp & 3) * 32;    // warp col origin (0..96)
    const int g    = lane >> 2;          // 0..7
    const int cc   = lane & 3;           // 0..3

    __shared__ float As[BK * BM];        // swizzled [k][m]
    __shared__ float Bs[BK * BN];        // swizzled [k][n]

    // A global-load mapping: m = tid>>1 (0..127), kf4h = tid&1, i loop over 4
    const int am   = tid >> 1;
    const int akh  = (tid & 1) * 4;
    // B global-load mapping: k = tid>>3 (0..31), n4 = tid&7, i loop over 4
    const int bk   = tid >> 3;
    const int bn4  = tid & 7;

    float acc[4][4][4];
    #pragma unroll
    for (int mt = 0; mt < 4; mt++)
        #pragma unroll
        for (int nt = 0; nt < 4; nt++)
            #pragma unroll
            for (int r = 0; r < 4; r++) acc[mt][nt][r] = 0.f;

    float4 av[4], bv[4];
    const int T = K / BK;

    // ---- prologue load (tile 0) ----
    {
        const float* Asrc; int kloc, ldA;
        if (0 < ksplit) { Asrc = A; kloc = 0; ldA = lda; }
        else            { Asrc = A2; kloc = -ksplit; ldA = lda2; }
        const float* ap = Asrc + (size_t)(row0 + am) * ldA + kloc + akh;
        #pragma unroll
        for (int i = 0; i < 4; i++) av[i] = *(const float4*)(ap + i * 8);
        const float* bp = Bw + (size_t)bk * ldb + col0 + bn4 * 4;
        #pragma unroll
        for (int i = 0; i < 4; i++) bv[i] = *(const float4*)(bp + i * 32);
    }

    for (int t = 0; t < T; t++) {
        // ---- store prefetched tile to smem (convert to tf32) ----
        #pragma unroll
        for (int i = 0; i < 4; i++) {
            int kb = i * 8 + akh;
            As[SWZ(kb + 0, am)] = __uint_as_float(f2tf32(av[i].x));
            As[SWZ(kb + 1, am)] = __uint_as_float(f2tf32(av[i].y));
            As[SWZ(kb + 2, am)] = __uint_as_float(f2tf32(av[i].z));
            As[SWZ(kb + 3, am)] = __uint_as_float(f2tf32(av[i].w));
        }
        #pragma unroll
        for (int i = 0; i < 4; i++) {
            int n = (bn4 + 8 * i) * 4;
            uint4 u;
            u.x = f2tf32(bv[i].x); u.y = f2tf32(bv[i].y);
            u.z = f2tf32(bv[i].z); u.w = f2tf32(bv[i].w);
            *(uint4*)&Bs[SWZ(bk, n)] = u;
        }
        __syncthreads();

        // ---- prefetch next tile ----
        if (t + 1 < T) {
            int k0 = (t + 1) * BK;
            const float* Asrc; int kloc, ldA;
            if (k0 < ksplit) { Asrc = A; kloc = k0; ldA = lda; }
            else             { Asrc = A2; kloc = k0 - ksplit; ldA = lda2; }
            const float* ap = Asrc + (size_t)(row0 + am) * ldA + kloc + akh;
            #pragma unroll
            for (int i = 0; i < 4; i++) av[i] = *(const float4*)(ap + i * 8);
            const float* bp = Bw + (size_t)(k0 + bk) * ldb + col0 + bn4 * 4;
            #pragma unroll
            for (int i = 0; i < 4; i++) bv[i] = *(const float4*)(bp + i * 32);
        }

        // ---- compute on current smem tile ----
        #pragma unroll
        for (int k8 = 0; k8 < 4; k8++) {
            const int k = k8 * 8 + cc;
            uint32_t bf[4][2];
            #pragma unroll
            for (int nt = 0; nt < 4; nt++) {
                int n = wn + nt * 8 + g;
                bf[nt][0] = __float_as_uint(Bs[SWZ(k, n)]);
                bf[nt][1] = __float_as_uint(Bs[SWZ(k + 4, n)]);
            }
            #pragma unroll
            for (int mt = 0; mt < 4; mt++) {
                int m = wm + mt * 16 + g;
                uint32_t a0 = __float_as_uint(As[SWZ(k, m)]);
                uint32_t a1 = __float_as_uint(As[SWZ(k, m + 8)]);
                uint32_t a2 = __float_as_uint(As[SWZ(k + 4, m)]);
                uint32_t a3 = __float_as_uint(As[SWZ(k + 4, m + 8)]);
                #pragma unroll
                for (int nt = 0; nt < 4; nt++)
                    mma_tf32(acc[mt][nt][0], acc[mt][nt][1], acc[mt][nt][2], acc[mt][nt][3],
                             a0, a1, a2, a3, bf[nt][0], bf[nt][1]);
            }
        }
        __syncthreads();
    }

    // ---- epilogue ----
    #pragma unroll
    for (int mt = 0; mt < 4; mt++) {
        int row = row0 + wm + mt * 16 + g;
        #pragma unroll
        for (int nt = 0; nt < 4; nt++) {
            int col = col0 + wn + nt * 8 + 2 * cc;
            float b0 = bias ? bias[col]     : 0.f;
            float b1 = bias ? bias[col + 1] : 0.f;
            float2 v0 = make_float2(acc[mt][nt][0] + b0, acc[mt][nt][1] + b1);
            float2 v1 = make_float2(acc[mt][nt][2] + b0, acc[mt][nt][3] + b1);
            *(float2*)(C + (size_t)row * ldc + col)       = v0;
            *(float2*)(C + (size_t)(row + 8) * ldc + col) = v1;
        }
    }
}

// ---------------- tiny action GEMM (K=32) into xc[:, 2048:3072] --------------
__global__ __launch_bounds__(256)
void act_gemm(const float* __restrict__ action, const float* __restrict__ W3,
              const float* __restrict__ b3, float* __restrict__ xc)
{
    int b = blockIdx.x;
    __shared__ float a_s[ACTD];
    int t = threadIdx.x;
    if (t < ACTD) {
        float v = action[(size_t)b * ACTD + t];
        float m = fabsf(v); m = m > 1.f ? m : 1.f;
        a_s[t] = v / m;
    }
    __syncthreads();
    for (int n = t; n < HID; n += 256) {
        float s = b3[n];
        #pragma unroll
        for (int k = 0; k < ACTD; k++) s = fmaf(a_s[k], W3[k * HID + n], s);
        xc[(size_t)b * (3 * HID) + 2 * HID + n] = s;
    }
}

// ---------------- rmsnorm + silu, in place on one 1024-wide segment of xc ----
__global__ __launch_bounds__(256)
void rms_silu(float* __restrict__ xc,
              const float* __restrict__ w1, const float* __restrict__ w2,
              const float* __restrict__ w3)
{
    int b = blockIdx.x, s = blockIdx.y;
    const float* w = (s == 0) ? w1 : (s == 1) ? w2 : w3;
    float* seg = xc + (size_t)b * (3 * HID) + (size_t)s * HID;
    int i0 = threadIdx.x * 4;
    float4 v = *(float4*)(seg + i0);
    float ss = v.x * v.x + v.y * v.y + v.z * v.z + v.w * v.w;
    float tot = block_sum(ss);
    float scale = rsqrtf(tot * (1.0f / HID) + EPSV);
    float4 g = *(const float4*)(w + i0);
    float4 o;
    float y;
    y = v.x * scale * g.x; o.x = y / (1.f + expf(-y));
    y = v.y * scale * g.y; o.y = y / (1.f + expf(-y));
    y = v.z * scale * g.z; o.z = y / (1.f + expf(-y));
    y = v.w * scale * g.w; o.w = y / (1.f + expf(-y));
    *(float4*)(seg + i0) = o;
}

// ---------------- rmsnorm over 8192 (H -> hn) --------------------------------
__global__ __launch_bounds__(256)
void rms_deter(const float* __restrict__ H, const float* __restrict__ gdyn,
               float* __restrict__ hn)
{
    int b = blockIdx.x;
    const float* row = H + (size_t)b * DETER;
    float4 v[8];
    float ss = 0.f;
    #pragma unroll
    for (int c = 0; c < 8; c++) {
        int d = threadIdx.x * 4 + c * 1024;
        v[c] = *(const float4*)(row + d);
        ss += v[c].x * v[c].x + v[c].y * v[c].y + v[c].z * v[c].z + v[c].w * v[c].w;
    }
    float tot = block_sum(ss);
    float scale = rsqrtf(tot * (1.0f / DETER) + EPSV);
    float* out = hn + (size_t)b * DETER;
    #pragma unroll
    for (int c = 0; c < 8; c++) {
        int d = threadIdx.x * 4 + c * 1024;
        float4 g = *(const float4*)(gdyn + d);
        float4 o;
        o.x = v[c].x * scale * g.x;
        o.y = v[c].y * scale * g.y;
        o.z = v[c].z * scale * g.z;
        o.w = v[c].w * scale * g.w;
        *(float4*)(out + d) = o;
    }
}

// ---------------- gates ------------------------------------------------------
__device__ __forceinline__ float sigf(float x) { return 1.f / (1.f + expf(-x)); }

__global__ __launch_bounds__(256)
void gates(const float* __restrict__ X, const float* __restrict__ deter,
           float* __restrict__ out)
{
    size_t t = (size_t)blockIdx.x * blockDim.x + threadIdx.x;
    size_t e = t * 4;
    int b = (int)(e / DETER);
    int d = (int)(e % DETER);
    int g = d >> 10, o = d & 1023;
    size_t xb = (size_t)b * (GRP * 3 * DPG) + (size_t)g * (3 * DPG) + o;
    float4 R  = *(const float4*)(X + xb);
    float4 Cc = *(const float4*)(X + xb + DPG);
    float4 U  = *(const float4*)(X + xb + 2 * DPG);
    float4 D  = *(const float4*)(deter + (size_t)b * DETER + d);
    float4 r;
    float rs, cd, up;
    rs = sigf(R.x); cd = tanhf(rs * Cc.x); up = sigf(U.x - 1.f); r.x = up * cd + (1.f - up) * D.x;
    rs = sigf(R.y); cd = tanhf(rs * Cc.y); up = sigf(U.y - 1.f); r.y = up * cd + (1.f - up) * D.y;
    rs = sigf(R.z); cd = tanhf(rs * Cc.z); up = sigf(U.z - 1.f); r.z = up * cd + (1.f - up) * D.z;
    rs = sigf(R.w); cd = tanhf(rs * Cc.w); up = sigf(U.w - 1.f); r.w = up * cd + (1.f - up) * D.w;
    *(float4*)(out + e) = r;
}

// ---------------- launch -----------------------------------------------------
extern "C" void kernel_launch(void* const* d_in, const int* in_sizes, int n_in,
                              void* d_out, int out_size)
{
    const float* deter  = (const float*)d_in[0];
    const float* stoch  = (const float*)d_in[1];
    const float* action = (const float*)d_in[2];
    const float* W1     = (const float*)d_in[3];
    const float* b1     = (const float*)d_in[4];
    const float* W2     = (const float*)d_in[5];
    const float* b2     = (const float*)d_in[6];
    const float* W3     = (const float*)d_in[7];
    const float* b3     = (const float*)d_in[8];
    const float* g1     = (const float*)d_in[9];
    const float* g2     = (const float*)d_in[10];
    const float* g3     = (const float*)d_in[11];
    const float* Wdyn   = (const float*)d_in[12];
    const float* gdyn   = (const float*)d_in[13];
    const float* Wout   = (const float*)d_in[14];
    float* out          = (float*)d_out;

    float *xc, *H, *hn, *X;
    cudaGetSymbolAddress((void**)&xc, g_xc);
    cudaGetSymbolAddress((void**)&H,  g_H);
    cudaGetSymbolAddress((void**)&hn, g_hn);
    cudaGetSymbolAddress((void**)&X,  g_X);

    // GEMM1: deter @ W1 + b1 -> xc[:, 0:1024]
    tgemm<<<dim3(HID / BN, BSZ / BM, 1), 256>>>(
        DETER, DETER, deter, DETER, 0, deter, DETER, 0,
        W1, HID, 0, b1, xc, 3 * HID, 0);

    // GEMM2: stoch @ W2 + b2 -> xc[:, 1024:2048]
    tgemm<<<dim3(HID / BN, BSZ / BM, 1), 256>>>(
        STOCH, STOCH, stoch, STOCH, 0, stoch, STOCH, 0,
        W2, HID, 0, b2, xc + HID, 3 * HID, 0);

    // GEMM3: norm(action) @ W3 + b3 -> xc[:, 2048:3072]
    act_gemm<<<BSZ, 256>>>(action, W3, b3, xc);

    // rmsnorm + silu on all three segments (in place)
    rms_silu<<<dim3(BSZ, 3), 256>>>(xc, g1, g2, g3);

    // GEMM4 (block-diagonal dyn): H[:, g*1024:(g+1)*1024] = [xc | deter_g] @ Wdyn[g]
    tgemm<<<dim3(DPG / BN, BSZ / BM, GRP), 256>>>(
        4096, 3 * HID,
        xc, 3 * HID, 0,
        deter, DETER, DPG,
        Wdyn, DPG, (long long)4096 * DPG,
        nullptr, H, DETER, DPG);

    // rmsnorm over 8192
    rms_deter<<<BSZ, 256>>>(H, gdyn, hn);

    // GEMM5 (block-diagonal out): X[:, g, :] = hn_g @ Wout[g]
    tgemm<<<dim3(3 * DPG / BN, BSZ / BM, GRP), 256>>>(
        DPG, DPG,
        hn, DETER, DPG,
        hn, DETER, DPG,
        Wout, 3 * DPG, (long long)DPG * 3 * DPG,
        nullptr, X, GRP * 3 * DPG, 3 * DPG);

    // gates
    size_t n4 = (size_t)BSZ * DETER / 4;
    gates<<<(unsigned)((n4 + 255) / 256), 256>>>(X, deter, out);
}

// round 5
// speedup vs baseline: 4.5063x; 1.5631x over previous
#include <cuda_runtime.h>
#include <cuda_fp16.h>
#include <math.h>
#include <stdint.h>

#define BSZ   2048
#define DETER 8192
#define STOCH 1024
#define ACTD  32
#define HID   1024
#define GRP   8
#define DPG   1024
#define EPSV  1e-6f

// ---------------- scratch (static device arrays; no allocations) -------------
__device__ float g_xc[BSZ * 3 * HID];
__device__ float g_H [BSZ * DETER];
__device__ float g_hn[BSZ * DETER];
__device__ float g_X [BSZ * GRP * 3 * DPG];
// transposed fp16 weights: rows are output-channel n, k-contiguous
__device__ __half g_W1T  [HID * DETER];          // [1024][8192]
__device__ __half g_W2T  [HID * STOCH];          // [1024][1024]
__device__ __half g_WdynT[GRP * DPG * 4096];     // [8][1024][4096]
__device__ __half g_WoutT[GRP * 3 * DPG * DPG];  // [8][3072][1024]

// ---------------- helpers ----------------------------------------------------
__device__ __forceinline__ uint32_t pkh2(float a, float b) {
    __half2 h = __floats2half2_rn(a, b);
    return *reinterpret_cast<uint32_t*>(&h);
}

__device__ __forceinline__ void mma_f16(float& c0, float& c1, float& c2, float& c3,
                                        uint32_t a0, uint32_t a1, uint32_t a2, uint32_t a3,
                                        uint32_t b0, uint32_t b1) {
    asm("mma.sync.aligned.m16n8k16.row.col.f32.f16.f16.f32 "
        "{%0,%1,%2,%3},{%4,%5,%6,%7},{%8,%9},{%0,%1,%2,%3};"
        : "+f"(c0), "+f"(c1), "+f"(c2), "+f"(c3)
        : "r"(a0), "r"(a1), "r"(a2), "r"(a3), "r"(b0), "r"(b1));
}

__device__ __forceinline__ float block_sum(float v) {
    __shared__ float red[32];
    int lane = threadIdx.x & 31, w = threadIdx.x >> 5;
    #pragma unroll
    for (int o = 16; o; o >>= 1) v += __shfl_xor_sync(0xffffffffu, v, o);
    if (lane == 0) red[w] = v;
    __syncthreads();
    int nw = blockDim.x >> 5;
    float s = (threadIdx.x < (unsigned)nw) ? red[threadIdx.x] : 0.f;
    if (w == 0) {
        #pragma unroll
        for (int o = 16; o; o >>= 1) s += __shfl_xor_sync(0xffffffffu, s, o);
        if (lane == 0) red[0] = s;
    }
    __syncthreads();
    return red[0];
}

// ---------------- FP16 tensor-core GEMM --------------------------------------
// C[z] (M x N) = A_cat[z] (M x K) * B[z]^T + bias, with BT as half rows [n][k].
// A cols [0,ksplit) from A (lda), rest from A2 (lda2). K % 32 == 0, ksplit % 32 == 0.
// Smem tile rows padded to 80 B (20 words) -> conflict-free operand LDS.
#define ROWB 80
#define TILEB (128 * ROWB)       // 10240 B per operand tile
#define STAGEB (2 * TILEB)       // A + B per stage

__global__ __launch_bounds__(256, 2)
void hgemm(int K, int ksplit,
           const float* __restrict__ A,  int lda,  long long sAz,
           const float* __restrict__ A2, int lda2, long long sA2z,
           const __half* __restrict__ BT, int ldb, long long sBz,
           const float* __restrict__ bias,
           float* __restrict__ C, int ldc, long long sCz)
{
    __shared__ char smem[2 * STAGEB];

    const int z = blockIdx.z;
    A  += (size_t)z * sAz;
    A2 += (size_t)z * sA2z;
    BT += (size_t)z * sBz;
    C  += (size_t)z * sCz;

    const int row0 = blockIdx.y * 128;
    const int col0 = blockIdx.x * 128;
    const int tid  = threadIdx.x;
    const int lane = tid & 31;
    const int warp = tid >> 5;
    const int wm   = (warp >> 2) * 64;
    const int wn   = (warp & 3) * 32;
    const int g    = lane >> 2;
    const int c    = lane & 3;

    // loader mapping: each thread owns one half-row segment (16 k-elements)
    const int am = tid >> 1;          // row (m or n), 0..127
    const int ah = tid & 1;           // k-half: 0 or 1 (x16 elements)

    float4 av[4];
    uint4  bv[2];

    const int T = K / 32;

    float acc[4][4][4];
    #pragma unroll
    for (int mt = 0; mt < 4; mt++)
        #pragma unroll
        for (int nt = 0; nt < 4; nt++)
            #pragma unroll
            for (int r = 0; r < 4; r++) acc[mt][nt][r] = 0.f;

    // ---- LDG of tile k0 into registers ----
    auto ldg_tile = [&](int k0) {
        const float* Asrc; int kloc, ldA;
        if (k0 < ksplit) { Asrc = A;  kloc = k0;          ldA = lda;  }
        else             { Asrc = A2; kloc = k0 - ksplit; ldA = lda2; }
        const float* ap = Asrc + (size_t)(row0 + am) * ldA + kloc + ah * 16;
        av[0] = *(const float4*)(ap);
        av[1] = *(const float4*)(ap + 4);
        av[2] = *(const float4*)(ap + 8);
        av[3] = *(const float4*)(ap + 12);
        const __half* bp = BT + (size_t)(col0 + am) * ldb + k0 + ah * 16;
        bv[0] = *(const uint4*)(bp);
        bv[1] = *(const uint4*)(bp + 8);
    };

    // ---- STS of registers into stage s (fp32 -> fp16 for A) ----
    auto sts_tile = [&](int s) {
        char* As = smem + s * STAGEB;
        char* Bs = As + TILEB;
        const uint32_t off = (uint32_t)(am * ROWB + ah * 32);
        uint4 u0, u1;
        u0.x = pkh2(av[0].x, av[0].y); u0.y = pkh2(av[0].z, av[0].w);
        u0.z = pkh2(av[1].x, av[1].y); u0.w = pkh2(av[1].z, av[1].w);
        u1.x = pkh2(av[2].x, av[2].y); u1.y = pkh2(av[2].z, av[2].w);
        u1.z = pkh2(av[3].x, av[3].y); u1.w = pkh2(av[3].z, av[3].w);
        *(uint4*)(As + off)      = u0;
        *(uint4*)(As + off + 16) = u1;
        *(uint4*)(Bs + off)      = bv[0];
        *(uint4*)(Bs + off + 16) = bv[1];
    };

    // ---- prologue ----
    ldg_tile(0);
    sts_tile(0);
    if (T > 1) ldg_tile(32);
    __syncthreads();

    for (int t = 0; t < T; t++) {
        const char* As = smem + (t & 1) * STAGEB;
        const char* Bs = As + TILEB;

        // compute current stage
        #pragma unroll
        for (int k16 = 0; k16 < 2; k16++) {
            const int kb = k16 * 32 + c * 4;   // byte offset of this thread's k-pair
            uint32_t bf[4][2];
            #pragma unroll
            for (int nt = 0; nt < 4; nt++) {
                const char* rb = Bs + (wn + nt * 8 + g) * ROWB + kb;
                bf[nt][0] = *(const uint32_t*)(rb);
                bf[nt][1] = *(const uint32_t*)(rb + 16);
            }
            #pragma unroll
            for (int mt = 0; mt < 4; mt++) {
                const int m = wm + mt * 16 + g;
                const char* r0 = As + m * ROWB + kb;
                const char* r1 = As + (m + 8) * ROWB + kb;
                uint32_t a0 = *(const uint32_t*)(r0);
                uint32_t a1 = *(const uint32_t*)(r1);
                uint32_t a2 = *(const uint32_t*)(r0 + 16);
                uint32_t a3 = *(const uint32_t*)(r1 + 16);
                #pragma unroll
                for (int nt = 0; nt < 4; nt++)
                    mma_f16(acc[mt][nt][0], acc[mt][nt][1], acc[mt][nt][2], acc[mt][nt][3],
                            a0, a1, a2, a3, bf[nt][0], bf[nt][1]);
            }
        }

        // stage t+1 was prefetched into regs: store it; then prefetch t+2
        if (t + 1 < T) sts_tile((t + 1) & 1);
        if (t + 2 < T) ldg_tile((t + 2) * 32);
        __syncthreads();
    }

    // ---- epilogue ----
    #pragma unroll
    for (int mt = 0; mt < 4; mt++) {
        int row = row0 + wm + mt * 16 + g;
        #pragma unroll
        for (int nt = 0; nt < 4; nt++) {
            int col = col0 + wn + nt * 8 + 2 * c;
            float b0 = bias ? bias[col]     : 0.f;
            float b1 = bias ? bias[col + 1] : 0.f;
            float2 v0 = make_float2(acc[mt][nt][0] + b0, acc[mt][nt][1] + b1);
            float2 v1 = make_float2(acc[mt][nt][2] + b0, acc[mt][nt][3] + b1);
            *(float2*)(C + (size_t)row * ldc + col)       = v0;
            *(float2*)(C + (size_t)(row + 8) * ldc + col) = v1;
        }
    }
}

// ---------------- weight transpose + fp16 convert ([R][C] -> half [C][R]) ----
__global__ __launch_bounds__(256)
void transpose_h(const float* __restrict__ in, __half* __restrict__ out, int R, int C)
{
    __shared__ float t[32][33];
    const int z = blockIdx.z;
    in  += (size_t)z * R * C;
    out += (size_t)z * R * C;
    int c0 = blockIdx.x * 32, r0 = blockIdx.y * 32;
    int tx = threadIdx.x & 31, ty = threadIdx.x >> 5;
    #pragma unroll
    for (int j = 0; j < 4; j++)
        t[ty + j * 8][tx] = in[(size_t)(r0 + ty + j * 8) * C + c0 + tx];
    __syncthreads();
    #pragma unroll
    for (int j = 0; j < 4; j++)
        out[(size_t)(c0 + ty + j * 8) * R + r0 + tx] = __float2half_rn(t[tx][ty + j * 8]);
}

// ---------------- tiny action GEMM (K=32) ------------------------------------
__global__ __launch_bounds__(256)
void act_gemm(const float* __restrict__ action, const float* __restrict__ W3,
              const float* __restrict__ b3, float* __restrict__ xc)
{
    int b = blockIdx.x;
    __shared__ float a_s[ACTD];
    int t = threadIdx.x;
    if (t < ACTD) {
        float v = action[(size_t)b * ACTD + t];
        float m = fabsf(v); m = m > 1.f ? m : 1.f;
        a_s[t] = v / m;
    }
    __syncthreads();
    for (int n = t; n < HID; n += 256) {
        float s = b3[n];
        #pragma unroll
        for (int k = 0; k < ACTD; k++) s = fmaf(a_s[k], W3[k * HID + n], s);
        xc[(size_t)b * (3 * HID) + 2 * HID + n] = s;
    }
}

// ---------------- rmsnorm + silu ---------------------------------------------
__global__ __launch_bounds__(256)
void rms_silu(float* __restrict__ xc,
              const float* __restrict__ w1, const float* __restrict__ w2,
              const float* __restrict__ w3)
{
    int b = blockIdx.x, s = blockIdx.y;
    const float* w = (s == 0) ? w1 : (s == 1) ? w2 : w3;
    float* seg = xc + (size_t)b * (3 * HID) + (size_t)s * HID;
    int i0 = threadIdx.x * 4;
    float4 v = *(float4*)(seg + i0);
    float ss = v.x * v.x + v.y * v.y + v.z * v.z + v.w * v.w;
    float tot = block_sum(ss);
    float scale = rsqrtf(tot * (1.0f / HID) + EPSV);
    float4 g = *(const float4*)(w + i0);
    float4 o; float y;
    y = v.x * scale * g.x; o.x = y / (1.f + expf(-y));
    y = v.y * scale * g.y; o.y = y / (1.f + expf(-y));
    y = v.z * scale * g.z; o.z = y / (1.f + expf(-y));
    y = v.w * scale * g.w; o.w = y / (1.f + expf(-y));
    *(float4*)(seg + i0) = o;
}

// ---------------- rmsnorm over 8192 ------------------------------------------
__global__ __launch_bounds__(256)
void rms_deter(const float* __restrict__ H, const float* __restrict__ gdyn,
               float* __restrict__ hn)
{
    int b = blockIdx.x;
    const float* row = H + (size_t)b * DETER;
    float4 v[8];
    float ss = 0.f;
    #pragma unroll
    for (int cc = 0; cc < 8; cc++) {
        int d = threadIdx.x * 4 + cc * 1024;
        v[cc] = *(const float4*)(row + d);
        ss += v[cc].x * v[cc].x + v[cc].y * v[cc].y + v[cc].z * v[cc].z + v[cc].w * v[cc].w;
    }
    float tot = block_sum(ss);
    float scale = rsqrtf(tot * (1.0f / DETER) + EPSV);
    float* out = hn + (size_t)b * DETER;
    #pragma unroll
    for (int cc = 0; cc < 8; cc++) {
        int d = threadIdx.x * 4 + cc * 1024;
        float4 g = *(const float4*)(gdyn + d);
        float4 o;
        o.x = v[cc].x * scale * g.x;
        o.y = v[cc].y * scale * g.y;
        o.z = v[cc].z * scale * g.z;
        o.w = v[cc].w * scale * g.w;
        *(float4*)(out + d) = o;
    }
}

// ---------------- gates ------------------------------------------------------
__device__ __forceinline__ float sigf(float x) { return 1.f / (1.f + expf(-x)); }

__global__ __launch_bounds__(256)
void gates(const float* __restrict__ X, const float* __restrict__ deter,
           float* __restrict__ out)
{
    size_t t = (size_t)blockIdx.x * blockDim.x + threadIdx.x;
    size_t e = t * 4;
    int b = (int)(e / DETER);
    int d = (int)(e % DETER);
    int g = d >> 10, o = d & 1023;
    size_t xb = (size_t)b * (GRP * 3 * DPG) + (size_t)g * (3 * DPG) + o;
    float4 R  = *(const float4*)(X + xb);
    float4 Cc = *(const float4*)(X + xb + DPG);
    float4 U  = *(const float4*)(X + xb + 2 * DPG);
    float4 D  = *(const float4*)(deter + (size_t)b * DETER + d);
    float4 r; float rs, cd, up;
    rs = sigf(R.x); cd = tanhf(rs * Cc.x); up = sigf(U.x - 1.f); r.x = up * cd + (1.f - up) * D.x;
    rs = sigf(R.y); cd = tanhf(rs * Cc.y); up = sigf(U.y - 1.f); r.y = up * cd + (1.f - up) * D.y;
    rs = sigf(R.z); cd = tanhf(rs * Cc.z); up = sigf(U.z - 1.f); r.z = up * cd + (1.f - up) * D.z;
    rs = sigf(R.w); cd = tanhf(rs * Cc.w); up = sigf(U.w - 1.f); r.w = up * cd + (1.f - up) * D.w;
    *(float4*)(out + e) = r;
}

// ---------------- launch -----------------------------------------------------
extern "C" void kernel_launch(void* const* d_in, const int* in_sizes, int n_in,
                              void* d_out, int out_size)
{
    const float* deter  = (const float*)d_in[0];
    const float* stoch  = (const float*)d_in[1];
    const float* action = (const float*)d_in[2];
    const float* W1     = (const float*)d_in[3];
    const float* b1     = (const float*)d_in[4];
    const float* W2     = (const float*)d_in[5];
    const float* b2     = (const float*)d_in[6];
    const float* W3     = (const float*)d_in[7];
    const float* b3     = (const float*)d_in[8];
    const float* g1     = (const float*)d_in[9];
    const float* g2     = (const float*)d_in[10];
    const float* g3     = (const float*)d_in[11];
    const float* Wdyn   = (const float*)d_in[12];
    const float* gdyn   = (const float*)d_in[13];
    const float* Wout   = (const float*)d_in[14];
    float* out          = (float*)d_out;

    float *xc, *H, *hn, *X;
    __half *W1T, *W2T, *WdynT, *WoutT;
    cudaGetSymbolAddress((void**)&xc,    g_xc);
    cudaGetSymbolAddress((void**)&H,     g_H);
    cudaGetSymbolAddress((void**)&hn,    g_hn);
    cudaGetSymbolAddress((void**)&X,     g_X);
    cudaGetSymbolAddress((void**)&W1T,   g_W1T);
    cudaGetSymbolAddress((void**)&W2T,   g_W2T);
    cudaGetSymbolAddress((void**)&WdynT, g_WdynT);
    cudaGetSymbolAddress((void**)&WoutT, g_WoutT);

    // weight transposes (fp16, k-contiguous rows)
    transpose_h<<<dim3(HID / 32, DETER / 32, 1), 256>>>(W1, W1T, DETER, HID);
    transpose_h<<<dim3(HID / 32, STOCH / 32, 1), 256>>>(W2, W2T, STOCH, HID);
    transpose_h<<<dim3(DPG / 32, 4096 / 32, GRP), 256>>>(Wdyn, WdynT, 4096, DPG);
    transpose_h<<<dim3(3 * DPG / 32, DPG / 32, GRP), 256>>>(Wout, WoutT, DPG, 3 * DPG);

    // GEMM1: deter @ W1 + b1 -> xc[:, 0:1024]
    hgemm<<<dim3(HID / 128, BSZ / 128, 1), 256>>>(
        DETER, DETER, deter, DETER, 0, deter, DETER, 0,
        W1T, DETER, 0, b1, xc, 3 * HID, 0);

    // GEMM2: stoch @ W2 + b2 -> xc[:, 1024:2048]
    hgemm<<<dim3(HID / 128, BSZ / 128, 1), 256>>>(
        STOCH, STOCH, stoch, STOCH, 0, stoch, STOCH, 0,
        W2T, STOCH, 0, b2, xc + HID, 3 * HID, 0);

    // GEMM3: norm(action) @ W3 + b3 -> xc[:, 2048:3072]
    act_gemm<<<BSZ, 256>>>(action, W3, b3, xc);

    // rmsnorm + silu on all three segments (in place)
    rms_silu<<<dim3(BSZ, 3), 256>>>(xc, g1, g2, g3);

    // GEMM4 (block-diagonal dyn): H[:, g*1024:(g+1)*1024] = [xc | deter_g] @ Wdyn[g]
    hgemm<<<dim3(DPG / 128, BSZ / 128, GRP), 256>>>(
        4096, 3 * HID,
        xc, 3 * HID, 0,
        deter, DETER, DPG,
        WdynT, 4096, (long long)DPG * 4096,
        nullptr, H, DETER, DPG);

    // rmsnorm over 8192
    rms_deter<<<BSZ, 256>>>(H, gdyn, hn);

    // GEMM5 (block-diagonal out): X[:, g, :] = hn_g @ Wout[g]
    hgemm<<<dim3(3 * DPG / 128, BSZ / 128, GRP), 256>>>(
        DPG, DPG,
        hn, DETER, DPG,
        hn, DETER, DPG,
        WoutT, DPG, (long long)3 * DPG * DPG,
        nullptr, X, GRP * 3 * DPG, 3 * DPG);

    // gates
    size_t n4 = (size_t)BSZ * DETER / 4;
    gates<<<(unsigned)((n4 + 255) / 256), 256>>>(X, deter, out);
}

// round 7
// speedup vs baseline: 5.9029x; 1.3099x over previous
#include <cuda_runtime.h>
#include <cuda_fp16.h>
#include <math.h>
#include <stdint.h>

#define BSZ   2048
#define DETER 8192
#define STOCH 1024
#define ACTD  32
#define HID   1024
#define GRP   8
#define DPG   1024
#define EPSV  1e-6f

// ---------------- scratch (static device arrays; no allocations) -------------
__device__ float  g_xc [BSZ * 3 * HID];            // pre-activation GEMM outputs (fp32)
__device__ float  g_H  [BSZ * DETER];              // dyn output pre-norm (fp32)
__device__ float  g_X  [BSZ * GRP * 3 * DPG];      // out block-matmul output (fp32)
__device__ __half g_xch[BSZ * 3 * HID];            // silu(rmsnorm(.)) activations
__device__ __half g_hnh[BSZ * DETER];              // rmsnorm(H)
__device__ __half g_deterh[BSZ * DETER];           // fp16 copy of deter
__device__ __half g_stochh[BSZ * STOCH];           // fp16 copy of stoch
// transposed fp16 weights: rows are output-channel n, k-contiguous
__device__ __half g_W1T  [HID * DETER];
__device__ __half g_W2T  [HID * STOCH];
__device__ __half g_WdynT[GRP * DPG * 4096];
__device__ __half g_WoutT[GRP * 3 * DPG * DPG];

// ---------------- helpers ----------------------------------------------------
__device__ __forceinline__ void mma_f16(float& c0, float& c1, float& c2, float& c3,
                                        uint32_t a0, uint32_t a1, uint32_t a2, uint32_t a3,
                                        uint32_t b0, uint32_t b1) {
    asm("mma.sync.aligned.m16n8k16.row.col.f32.f16.f16.f32 "
        "{%0,%1,%2,%3},{%4,%5,%6,%7},{%8,%9},{%0,%1,%2,%3};"
        : "+f"(c0), "+f"(c1), "+f"(c2), "+f"(c3)
        : "r"(a0), "r"(a1), "r"(a2), "r"(a3), "r"(b0), "r"(b1));
}

#define CP_ASYNC16(s, g) \
    asm volatile("cp.async.cg.shared.global [%0], [%1], 16;" :: "r"(s), "l"(g) : "memory")
#define CP_COMMIT() asm volatile("cp.async.commit_group;" ::: "memory")
#define CP_WAIT1()  asm volatile("cp.async.wait_group 1;" ::: "memory")
#define CP_WAIT0()  asm volatile("cp.async.wait_group 0;" ::: "memory")

__device__ __forceinline__ float block_sum(float v) {
    __shared__ float red[32];
    int lane = threadIdx.x & 31, w = threadIdx.x >> 5;
    #pragma unroll
    for (int o = 16; o; o >>= 1) v += __shfl_xor_sync(0xffffffffu, v, o);
    if (lane == 0) red[w] = v;
    __syncthreads();
    int nw = blockDim.x >> 5;
    float s = (threadIdx.x < (unsigned)nw) ? red[threadIdx.x] : 0.f;
    if (w == 0) {
        #pragma unroll
        for (int o = 16; o; o >>= 1) s += __shfl_xor_sync(0xffffffffu, s, o);
        if (lane == 0) red[0] = s;
    }
    __syncthreads();
    return red[0];
}

// ---------------- FP16 tensor-core GEMM (cp.async 3-stage) -------------------
// C[z] (M x N) = A_cat[z] (M x K) * B[z]^T + bias; all operands fp16 in gmem.
// A cols [0,ksplit) from A (lda), rest from A2 (lda2). K % 32 == 0, ksplit % 32 == 0.
// Smem tile rows padded to 80 B -> conflict-free operand LDS.
#define ROWB 80
#define TILEB (128 * ROWB)          // 10240 B per operand tile
#define STAGEB (2 * TILEB)          // A + B per stage
#define NSTAGE 3
#define GEMM_SMEM (NSTAGE * STAGEB) // 61440 B

__global__ __launch_bounds__(256, 2)
void hgemm(int K, int ksplit,
           const __half* __restrict__ A,  int lda,  long long sAz,
           const __half* __restrict__ A2, int lda2, long long sA2z,
           const __half* __restrict__ BT, int ldb,  long long sBz,
           const float* __restrict__ bias,
           float* __restrict__ C, int ldc, long long sCz)
{
    extern __shared__ char smem[];

    const int z = blockIdx.z;
    A  += (size_t)z * sAz;
    A2 += (size_t)z * sA2z;
    BT += (size_t)z * sBz;
    C  += (size_t)z * sCz;

    const int row0 = blockIdx.y * 128;
    const int col0 = blockIdx.x * 128;
    const int tid  = threadIdx.x;
    const int lane = tid & 31;
    const int warp = tid >> 5;
    const int wm   = (warp >> 2) * 64;
    const int wn   = (warp & 3) * 32;
    const int g    = lane >> 2;
    const int c    = lane & 3;

    const uint32_t sb = (uint32_t)__cvta_generic_to_shared(smem);

    // loader mapping: thread owns one 32-byte k-segment of one row (A and B)
    const int am = tid >> 1;           // row 0..127
    const int ah = tid & 1;            // k-half (16 elements)

    const int T = K / 32;

    auto issue_tile = [&](int t) {
        const int k0 = t * 32;
        const __half* Asrc; int kloc, ldA;
        if (k0 < ksplit) { Asrc = A;  kloc = k0;          ldA = lda;  }
        else             { Asrc = A2; kloc = k0 - ksplit; ldA = lda2; }
        const __half* ap = Asrc + (size_t)(row0 + am) * ldA + kloc + ah * 16;
        const __half* bp = BT + (size_t)(col0 + am) * ldb + k0 + ah * 16;
        uint32_t s = sb + (t % NSTAGE) * STAGEB + am * ROWB + ah * 32;
        CP_ASYNC16(s,              ap);
        CP_ASYNC16(s + 16,         ap + 8);
        CP_ASYNC16(s + TILEB,      bp);
        CP_ASYNC16(s + TILEB + 16, bp + 8);
        CP_COMMIT();
    };

    float acc[4][4][4];
    #pragma unroll
    for (int mt = 0; mt < 4; mt++)
        #pragma unroll
        for (int nt = 0; nt < 4; nt++)
            #pragma unroll
            for (int r = 0; r < 4; r++) acc[mt][nt][r] = 0.f;

    issue_tile(0);
    if (T > 1) issue_tile(1);

    for (int t = 0; t < T; t++) {
        if (t + 1 < T) { CP_WAIT1(); } else { CP_WAIT0(); }
        __syncthreads();

        const char* As = smem + (t % NSTAGE) * STAGEB;
        const char* Bs = As + TILEB;

        #pragma unroll
        for (int k16 = 0; k16 < 2; k16++) {
            const int kb = k16 * 32 + c * 4;
            uint32_t bf[4][2];
            #pragma unroll
            for (int nt = 0; nt < 4; nt++) {
                const char* rb = Bs + (wn + nt * 8 + g) * ROWB + kb;
                bf[nt][0] = *(const uint32_t*)(rb);
                bf[nt][1] = *(const uint32_t*)(rb + 16);
            }
            #pragma unroll
            for (int mt = 0; mt < 4; mt++) {
                const int m = wm + mt * 16 + g;
                const char* r0 = As + m * ROWB + kb;
                const char* r1 = As + (m + 8) * ROWB + kb;
                uint32_t a0 = *(const uint32_t*)(r0);
                uint32_t a1 = *(const uint32_t*)(r1);
                uint32_t a2 = *(const uint32_t*)(r0 + 16);
                uint32_t a3 = *(const uint32_t*)(r1 + 16);
                #pragma unroll
                for (int nt = 0; nt < 4; nt++)
                    mma_f16(acc[mt][nt][0], acc[mt][nt][1], acc[mt][nt][2], acc[mt][nt][3],
                            a0, a1, a2, a3, bf[nt][0], bf[nt][1]);
            }
        }

        if (t + 2 < T) issue_tile(t + 2);
    }

    // ---- epilogue ----
    #pragma unroll
    for (int mt = 0; mt < 4; mt++) {
        int row = row0 + wm + mt * 16 + g;
        #pragma unroll
        for (int nt = 0; nt < 4; nt++) {
            int col = col0 + wn + nt * 8 + 2 * c;
            float b0 = bias ? bias[col]     : 0.f;
            float b1 = bias ? bias[col + 1] : 0.f;
            float2 v0 = make_float2(acc[mt][nt][0] + b0, acc[mt][nt][1] + b1);
            float2 v1 = make_float2(acc[mt][nt][2] + b0, acc[mt][nt][3] + b1);
            *(float2*)(C + (size_t)row * ldc + col)       = v0;
            *(float2*)(C + (size_t)(row + 8) * ldc + col) = v1;
        }
    }
}

// ---------------- weight transpose + fp16 convert ([R][C] -> half [C][R]) ----
__global__ __launch_bounds__(256)
void transpose_h(const float* __restrict__ in, __half* __restrict__ out, int R, int C)
{
    __shared__ float t[32][33];
    const int z = blockIdx.z;
    in  += (size_t)z * R * C;
    out += (size_t)z * R * C;
    int c0 = blockIdx.x * 32, r0 = blockIdx.y * 32;
    int tx = threadIdx.x & 31, ty = threadIdx.x >> 5;
    #pragma unroll
    for (int j = 0; j < 4; j++)
        t[ty + j * 8][tx] = in[(size_t)(r0 + ty + j * 8) * C + c0 + tx];
    __syncthreads();
    #pragma unroll
    for (int j = 0; j < 4; j++)
        out[(size_t)(c0 + ty + j * 8) * R + r0 + tx] = __float2half_rn(t[tx][ty + j * 8]);
}

// ---------------- fp32 -> fp16 elementwise convert ---------------------------
__global__ __launch_bounds__(256)
void f2h(const float* __restrict__ in, __half* __restrict__ out, size_t n4)
{
    size_t i = (size_t)blockIdx.x * blockDim.x + threadIdx.x;
    if (i >= n4) return;
    float4 v = *(const float4*)(in + i * 4);
    __half2 h0 = __floats2half2_rn(v.x, v.y);
    __half2 h1 = __floats2half2_rn(v.z, v.w);
    *(uint2*)(out + i * 4) = make_uint2(*(uint32_t*)&h0, *(uint32_t*)&h1);
}

// ---------------- tiny action GEMM (K=32) ------------------------------------
__global__ __launch_bounds__(256)
void act_gemm(const float* __restrict__ action, const float* __restrict__ W3,
              const float* __restrict__ b3, float* __restrict__ xc)
{
    int b = blockIdx.x;
    __shared__ float a_s[ACTD];
    int t = threadIdx.x;
    if (t < ACTD) {
        float v = action[(size_t)b * ACTD + t];
        float m = fabsf(v); m = m > 1.f ? m : 1.f;
        a_s[t] = v / m;
    }
    __syncthreads();
    for (int n = t; n < HID; n += 256) {
        float s = b3[n];
        #pragma unroll
        for (int k = 0; k < ACTD; k++) s = fmaf(a_s[k], W3[k * HID + n], s);
        xc[(size_t)b * (3 * HID) + 2 * HID + n] = s;
    }
}

// ---------------- rmsnorm + silu -> fp16 --------------------------------------
__global__ __launch_bounds__(256)
void rms_silu(const float* __restrict__ xc, __half* __restrict__ xch,
              const float* __restrict__ w1, const float* __restrict__ w2,
              const float* __restrict__ w3)
{
    int b = blockIdx.x, s = blockIdx.y;
    const float* w = (s == 0) ? w1 : (s == 1) ? w2 : w3;
    const float* seg = xc + (size_t)b * (3 * HID) + (size_t)s * HID;
    __half* oseg = xch + (size_t)b * (3 * HID) + (size_t)s * HID;
    int i0 = threadIdx.x * 4;
    float4 v = *(const float4*)(seg + i0);
    float ss = v.x * v.x + v.y * v.y + v.z * v.z + v.w * v.w;
    float tot = block_sum(ss);
    float scale = rsqrtf(tot * (1.0f / HID) + EPSV);
    float4 g = *(const float4*)(w + i0);
    float o0, o1, o2, o3; float y;
    y = v.x * scale * g.x; o0 = y / (1.f + expf(-y));
    y = v.y * scale * g.y; o1 = y / (1.f + expf(-y));
    y = v.z * scale * g.z; o2 = y / (1.f + expf(-y));
    y = v.w * scale * g.w; o3 = y / (1.f + expf(-y));
    __half2 h0 = __floats2half2_rn(o0, o1);
    __half2 h1 = __floats2half2_rn(o2, o3);
    *(uint2*)(oseg + i0) = make_uint2(*(uint32_t*)&h0, *(uint32_t*)&h1);
}

// ---------------- rmsnorm over 8192 -> fp16 ----------------------------------
__global__ __launch_bounds__(256)
void rms_deter(const float* __restrict__ H, const float* __restrict__ gdyn,
               __half* __restrict__ hnh)
{
    int b = blockIdx.x;
    const float* row = H + (size_t)b * DETER;
    float4 v[8];
    float ss = 0.f;
    #pragma unroll
    for (int cc = 0; cc < 8; cc++) {
        int d = threadIdx.x * 4 + cc * 1024;
        v[cc] = *(const float4*)(row + d);
        ss += v[cc].x * v[cc].x + v[cc].y * v[cc].y + v[cc].z * v[cc].z + v[cc].w * v[cc].w;
    }
    float tot = block_sum(ss);
    float scale = rsqrtf(tot * (1.0f / DETER) + EPSV);
    __half* out = hnh + (size_t)b * DETER;
    #pragma unroll
    for (int cc = 0; cc < 8; cc++) {
        int d = threadIdx.x * 4 + cc * 1024;
        float4 g = *(const float4*)(gdyn + d);
        __half2 h0 = __floats2half2_rn(v[cc].x * scale * g.x, v[cc].y * scale * g.y);
        __half2 h1 = __floats2half2_rn(v[cc].z * scale * g.z, v[cc].w * scale * g.w);
        *(uint2*)(out + d) = make_uint2(*(uint32_t*)&h0, *(uint32_t*)&h1);
    }
}

// ---------------- gates ------------------------------------------------------
__device__ __forceinline__ float sigf(float x) { return 1.f / (1.f + expf(-x)); }

__global__ __launch_bounds__(256)
void gates(const float* __restrict__ X, const float* __restrict__ deter,
           float* __restrict__ out)
{
    size_t t = (size_t)blockIdx.x * blockDim.x + threadIdx.x;
    size_t e = t * 4;
    int b = (int)(e / DETER);
    int d = (int)(e % DETER);
    int g = d >> 10, o = d & 1023;
    size_t xb = (size_t)b * (GRP * 3 * DPG) + (size_t)g * (3 * DPG) + o;
    float4 R  = *(const float4*)(X + xb);
    float4 Cc = *(const float4*)(X + xb + DPG);
    float4 U  = *(const float4*)(X + xb + 2 * DPG);
    float4 D  = *(const float4*)(deter + (size_t)b * DETER + d);
    float4 r; float rs, cd, up;
    rs = sigf(R.x); cd = tanhf(rs * Cc.x); up = sigf(U.x - 1.f); r.x = up * cd + (1.f - up) * D.x;
    rs = sigf(R.y); cd = tanhf(rs * Cc.y); up = sigf(U.y - 1.f); r.y = up * cd + (1.f - up) * D.y;
    rs = sigf(R.z); cd = tanhf(rs * Cc.z); up = sigf(U.z - 1.f); r.z = up * cd + (1.f - up) * D.z;
    rs = sigf(R.w); cd = tanhf(rs * Cc.w); up = sigf(U.w - 1.f); r.w = up * cd + (1.f - up) * D.w;
    *(float4*)(out + e) = r;
}

// ---------------- launch -----------------------------------------------------
extern "C" void kernel_launch(void* const* d_in, const int* in_sizes, int n_in,
                              void* d_out, int out_size)
{
    const float* deter  = (const float*)d_in[0];
    const float* stoch  = (const float*)d_in[1];
    const float* action = (const float*)d_in[2];
    const float* W1     = (const float*)d_in[3];
    const float* b1     = (const float*)d_in[4];
    const float* W2     = (const float*)d_in[5];
    const float* b2     = (const float*)d_in[6];
    const float* W3     = (const float*)d_in[7];
    const float* b3     = (const float*)d_in[8];
    const float* g1     = (const float*)d_in[9];
    const float* g2     = (const float*)d_in[10];
    const float* g3     = (const float*)d_in[11];
    const float* Wdyn   = (const float*)d_in[12];
    const float* gdyn   = (const float*)d_in[13];
    const float* Wout   = (const float*)d_in[14];
    float* out          = (float*)d_out;

    float *xc, *H, *X;
    __half *xch, *hnh, *deterh, *stochh, *W1T, *W2T, *WdynT, *WoutT;
    cudaGetSymbolAddress((void**)&xc,     g_xc);
    cudaGetSymbolAddress((void**)&H,      g_H);
    cudaGetSymbolAddress((void**)&X,      g_X);
    cudaGetSymbolAddress((void**)&xch,    g_xch);
    cudaGetSymbolAddress((void**)&hnh,    g_hnh);
    cudaGetSymbolAddress((void**)&deterh, g_deterh);
    cudaGetSymbolAddress((void**)&stochh, g_stochh);
    cudaGetSymbolAddress((void**)&W1T,    g_W1T);
    cudaGetSymbolAddress((void**)&W2T,    g_W2T);
    cudaGetSymbolAddress((void**)&WdynT,  g_WdynT);
    cudaGetSymbolAddress((void**)&WoutT,  g_WoutT);

    static bool attr_done = false;
    cudaFuncSetAttribute(hgemm, cudaFuncAttributeMaxDynamicSharedMemorySize, GEMM_SMEM);
    (void)attr_done;

    // fp16 conversions of inputs + weight transposes
    f2h<<<(unsigned)((BSZ * (size_t)DETER / 4 + 255) / 256), 256>>>(deter, deterh, BSZ * (size_t)DETER / 4);
    f2h<<<(unsigned)((BSZ * (size_t)STOCH / 4 + 255) / 256), 256>>>(stoch, stochh, BSZ * (size_t)STOCH / 4);
    transpose_h<<<dim3(HID / 32, DETER / 32, 1), 256>>>(W1, W1T, DETER, HID);
    transpose_h<<<dim3(HID / 32, STOCH / 32, 1), 256>>>(W2, W2T, STOCH, HID);
    transpose_h<<<dim3(DPG / 32, 4096 / 32, GRP), 256>>>(Wdyn, WdynT, 4096, DPG);
    transpose_h<<<dim3(3 * DPG / 32, DPG / 32, GRP), 256>>>(Wout, WoutT, DPG, 3 * DPG);

    // GEMM1: deter @ W1 + b1 -> xc[:, 0:1024]
    hgemm<<<dim3(HID / 128, BSZ / 128, 1), 256, GEMM_SMEM>>>(
        DETER, DETER, deterh, DETER, 0, deterh, DETER, 0,
        W1T, DETER, 0, b1, xc, 3 * HID, 0);

    // GEMM2: stoch @ W2 + b2 -> xc[:, 1024:2048]
    hgemm<<<dim3(HID / 128, BSZ / 128, 1), 256, GEMM_SMEM>>>(
        STOCH, STOCH, stochh, STOCH, 0, stochh, STOCH, 0,
        W2T, STOCH, 0, b2, xc + HID, 3 * HID, 0);

    // GEMM3: norm(action) @ W3 + b3 -> xc[:, 2048:3072]
    act_gemm<<<BSZ, 256>>>(action, W3, b3, xc);

    // rmsnorm + silu -> fp16 activations
    rms_silu<<<dim3(BSZ, 3), 256>>>(xc, xch, g1, g2, g3);

    // GEMM4 (block-diagonal dyn): H[:, g*1024:(g+1)*1024] = [xc | deter_g] @ Wdyn[g]
    hgemm<<<dim3(DPG / 128, BSZ / 128, GRP), 256, GEMM_SMEM>>>(
        4096, 3 * HID,
        xch, 3 * HID, 0,
        deterh, DETER, DPG,
        WdynT, 4096, (long long)DPG * 4096,
        nullptr, H, DETER, DPG);

    // rmsnorm over 8192 -> fp16
    rms_deter<<<BSZ, 256>>>(H, gdyn, hnh);

    // GEMM5 (block-diagonal out): X[:, g, :] = hn_g @ Wout[g]
    hgemm<<<dim3(3 * DPG / 128, BSZ / 128, GRP), 256, GEMM_SMEM>>>(
        DPG, DPG,
        hnh, DETER, DPG,
        hnh, DETER, DPG,
        WoutT, DPG, (long long)3 * DPG * DPG,
        nullptr, X, GRP * 3 * DPG, 3 * DPG);

    // gates
    size_t n4 = (size_t)BSZ * DETER / 4;
    gates<<<(unsigned)((n4 + 255) / 256), 256>>>(X, deter, out);
}